// round 4
// baseline (speedup 1.0000x reference)
#include <cuda_runtime.h>
#include <cuda_bf16.h>
#include <cstdint>

// ---------------- problem constants ----------------
#define NEXP 64
#define DIM  2048
#define HID  1024
#define TOK  16384
#define TPE  256

// scratch: SwiGLU intermediate h [TOK, HID] (tf32-rounded fp32) + pre-rounded X
__device__ float g_h[(size_t)TOK * HID];
__device__ float g_x[(size_t)TOK * DIM];

// ---------------- helpers ----------------
__device__ __forceinline__ uint32_t smem_u32(const void* p) {
    uint32_t a;
    asm("{ .reg .u64 t; cvta.to.shared.u64 t, %1; cvt.u32.u64 %0, t; }" : "=r"(a) : "l"(p));
    return a;
}
// round-to-nearest tf32 conversion (unbiased; critical for 1e-3 tolerance)
__device__ __forceinline__ uint32_t f2tf32(float x) {
    uint32_t r;
    asm("cvt.rna.tf32.f32 %0, %1;" : "=r"(r) : "f"(x));
    return r;
}

#define SWZ(x) ((x) ^ (((x) >> 3) & 0x70))

__device__ __forceinline__ void cp16(uint32_t dst, const void* src) {
    asm volatile("cp.async.cg.shared.global [%0], [%1], 16;" :: "r"(dst), "l"(src));
}
#define CP_COMMIT() asm volatile("cp.async.commit_group;" ::: "memory")
#define CP_WAIT1()  asm volatile("cp.async.wait_group 1;" ::: "memory")

// ldmatrix x4: loads four 8x4 tf32 blocks (each 8 rows x 16B)
__device__ __forceinline__ void ldsm4(uint32_t* f, uint32_t addr) {
    asm volatile("ldmatrix.sync.aligned.m8n8.x4.shared.b16 {%0,%1,%2,%3}, [%4];"
                 : "=r"(f[0]), "=r"(f[1]), "=r"(f[2]), "=r"(f[3]) : "r"(addr));
}

// mma m16n8k8 tf32, D += A*B
__device__ __forceinline__ void mma8(float* d, const uint32_t* a, uint32_t b0, uint32_t b1) {
    asm volatile("mma.sync.aligned.m16n8k8.row.col.f32.tf32.tf32.f32 "
                 "{%0,%1,%2,%3},{%4,%5,%6,%7},{%8,%9},{%0,%1,%2,%3};"
                 : "+f"(d[0]), "+f"(d[1]), "+f"(d[2]), "+f"(d[3])
                 : "r"(a[0]), "r"(a[1]), "r"(a[2]), "r"(a[3]), "r"(b0), "r"(b1));
}

__device__ __forceinline__ float silu(float v) {
    return v / (1.0f + __expf(-v));
}

// ---------------- smem layout ----------------
#define DN_BROW   136
#define DN_STAGE  33792
#define DN_SMEM   (3 * DN_STAGE)       // 101376
#define UP_BROW   72
#define UP_B1OFF  16384
#define UP_B3OFF  25600
#define UP_STAGE  34816
#define UP_SMEM   (3 * UP_STAGE)       // 104448

// ======================================================================
// Kernel 0: pre-round X to tf32 (so mainloop A-fragments need no cvt:
// HW truncation of an rna-rounded value is the identity)
// ======================================================================
__global__ __launch_bounds__(256)
void preround_kernel(const float* __restrict__ x)
{
    size_t i = (size_t)(blockIdx.x * 256 + threadIdx.x);
    size_t stride = (size_t)gridDim.x * 256;
    const size_t n4 = (size_t)TOK * DIM / 4;
    float4* dst = (float4*)g_x;
    const float4* src = (const float4*)x;
    for (; i < n4; i += stride) {
        float4 v = src[i];
        float4 t;
        t.x = __uint_as_float(f2tf32(v.x));
        t.y = __uint_as_float(f2tf32(v.y));
        t.z = __uint_as_float(f2tf32(v.z));
        t.w = __uint_as_float(f2tf32(v.w));
        dst[i] = t;
    }
}

// ======================================================================
// Kernel A: h = silu(X@W1) * (X@W3) per expert
// CTA: 128m x 64n (both W1,W3). 8 warps 2m x 4n; warp tile 64m x 16n per GEMM.
// grid = 64 * 2 * 16 = 2048
// ======================================================================
__global__ __launch_bounds__(256, 2)
void moe_up_kernel(const float* __restrict__ w1,
                   const float* __restrict__ w3)
{
    extern __shared__ __align__(1024) char smem[];
    const uint32_t sbase = smem_u32(smem);
    const int tid  = threadIdx.x;
    const int lane = tid & 31;
    const int wid  = tid >> 5;
    const int bid  = blockIdx.x;
    const int e    = bid >> 5;
    const int rem  = bid & 31;
    const int mt   = rem & 1;
    const int nt   = rem >> 1;       // 16 tiles of 64

    const float* xb  = g_x + (size_t)(e * TPE + mt * 128) * DIM;
    const float* w1b = w1 + (size_t)e * DIM * HID + nt * 64;
    const float* w3b = w3 + (size_t)e * DIM * HID + nt * 64;

    const int wm = wid >> 2, wn = wid & 3;
    const int mbase = wm * 64, nbase = wn * 16;
    const int blk = lane >> 3, r = lane & 7;

    const int am = tid >> 3, aq = tid & 7;   // A: rows am + j*32, chunk aq
    const int bk = tid >> 4, bq = tid & 15;  // B: rows bk + j*16, chunk bq

    auto issue = [&](int s) {
        const uint32_t buf = sbase + (uint32_t)(s % 3) * UP_STAGE;
        const int k0 = s * 32;
        #pragma unroll
        for (int j = 0; j < 4; j++) {
            int m = am + j * 32;
            cp16(buf + SWZ(m * 128 + aq * 16), xb + (size_t)m * DIM + k0 + aq * 4);
        }
        #pragma unroll
        for (int j = 0; j < 2; j++) {
            int k = bk + j * 16;
            cp16(buf + UP_B1OFF + k * 288 + bq * 16, w1b + (size_t)(k0 + k) * HID + bq * 4);
            cp16(buf + UP_B3OFF + k * 288 + bq * 16, w3b + (size_t)(k0 + k) * HID + bq * 4);
        }
    };

    float acc1[4][2][4], acc3[4][2][4];
    #pragma unroll
    for (int i = 0; i < 4; i++)
        #pragma unroll
        for (int j = 0; j < 2; j++)
            #pragma unroll
            for (int k = 0; k < 4; k++) { acc1[i][j][k] = 0.f; acc3[i][j][k] = 0.f; }

    issue(0); CP_COMMIT();
    issue(1); CP_COMMIT();

    const int kb = lane & 3, nq = lane >> 2;
    const int NS = DIM / 32;   // 64
    #pragma unroll 1
    for (int s = 0; s < NS; s++) {
        CP_WAIT1();
        __syncthreads();
        const uint32_t aA = sbase + (uint32_t)(s % 3) * UP_STAGE;
        const float* B1p = (const float*)(smem + (s % 3) * UP_STAGE + UP_B1OFF);
        const float* B3p = (const float*)(smem + (s % 3) * UP_STAGE + UP_B3OFF);
        #pragma unroll
        for (int kk = 0; kk < 4; kk++) {
            uint32_t af[4][4];
            #pragma unroll
            for (int m2 = 0; m2 < 4; m2++)
                ldsm4(af[m2], aA + SWZ((mbase + m2 * 16 + (blk & 1) * 8 + r) * 128 + kk * 32 + (blk >> 1) * 16));
            uint32_t b10[2], b11[2], b30[2], b31[2];
            #pragma unroll
            for (int p = 0; p < 2; p++) {
                int n = nbase + p * 8 + nq;
                int k = kk * 8 + kb;
                b10[p] = f2tf32(B1p[k * UP_BROW + n]);
                b11[p] = f2tf32(B1p[(k + 4) * UP_BROW + n]);
                b30[p] = f2tf32(B3p[k * UP_BROW + n]);
                b31[p] = f2tf32(B3p[(k + 4) * UP_BROW + n]);
            }
            #pragma unroll
            for (int m2 = 0; m2 < 4; m2++)
                #pragma unroll
                for (int p = 0; p < 2; p++) {
                    mma8(acc1[m2][p], af[m2], b10[p], b11[p]);
                    mma8(acc3[m2][p], af[m2], b30[p], b31[p]);
                }
        }
        if (s + 2 < NS) issue(s + 2);
        CP_COMMIT();
    }

    // fused SwiGLU epilogue -> g_h, pre-rounded to tf32 (identity under later truncation)
    const int g = lane >> 2, t4 = lane & 3;
    float* hb = g_h + (size_t)(e * TPE + mt * 128) * HID + nt * 64;
    #pragma unroll
    for (int m2 = 0; m2 < 4; m2++) {
        #pragma unroll
        for (int p = 0; p < 2; p++) {
            int row = mbase + m2 * 16 + g;
            int col = nbase + p * 8 + 2 * t4;
            float* r0 = hb + (size_t)row * HID + col;
            float* r1 = r0 + 8 * HID;
            *(float2*)r0 = make_float2(
                __uint_as_float(f2tf32(silu(acc1[m2][p][0]) * acc3[m2][p][0])),
                __uint_as_float(f2tf32(silu(acc1[m2][p][1]) * acc3[m2][p][1])));
            *(float2*)r1 = make_float2(
                __uint_as_float(f2tf32(silu(acc1[m2][p][2]) * acc3[m2][p][2])),
                __uint_as_float(f2tf32(silu(acc1[m2][p][3]) * acc3[m2][p][3])));
        }
    }
}

// ======================================================================
// Kernel B: out = h @ W2 per expert
// CTA: 128m x 128n. 8 warps 2m x 4n; warp tile 64m x 32n.
// grid = 64 * 2 * 16 = 2048
// ======================================================================
__global__ __launch_bounds__(256, 2)
void moe_down_kernel(const float* __restrict__ w2, float* __restrict__ out)
{
    extern __shared__ __align__(1024) char smem[];
    const uint32_t sbase = smem_u32(smem);
    const int tid  = threadIdx.x;
    const int lane = tid & 31;
    const int wid  = tid >> 5;
    const int bid  = blockIdx.x;
    const int e    = bid >> 5;
    const int rem  = bid & 31;
    const int mt   = rem & 1;
    const int nt   = rem >> 1;       // 16 tiles of 128

    const float* hb  = g_h + (size_t)(e * TPE + mt * 128) * HID;
    const float* w2b = w2 + (size_t)e * HID * DIM + nt * 128;

    const int wm = wid >> 2, wn = wid & 3;
    const int mbase = wm * 64, nbase = wn * 32;
    const int blk = lane >> 3, r = lane & 7;

    const int am = tid >> 3, aq = tid & 7;   // A rows am + j*32
    const int bk = tid >> 5, bq = tid & 31;  // B rows bk + j*8, chunk bq

    auto issue = [&](int s) {
        const uint32_t buf = sbase + (uint32_t)(s % 3) * DN_STAGE;
        const int k0 = s * 32;
        #pragma unroll
        for (int j = 0; j < 4; j++) {
            int m = am + j * 32;
            cp16(buf + SWZ(m * 128 + aq * 16), hb + (size_t)m * HID + k0 + aq * 4);
        }
        #pragma unroll
        for (int j = 0; j < 4; j++) {
            int k = bk + j * 8;
            cp16(buf + 16384 + k * 544 + bq * 16, w2b + (size_t)(k0 + k) * DIM + bq * 4);
        }
    };

    float acc[4][4][4];
    #pragma unroll
    for (int i = 0; i < 4; i++)
        #pragma unroll
        for (int j = 0; j < 4; j++)
            #pragma unroll
            for (int k = 0; k < 4; k++) acc[i][j][k] = 0.f;

    issue(0); CP_COMMIT();
    issue(1); CP_COMMIT();

    const int kb = lane & 3, nq = lane >> 2;
    const int NS = HID / 32;   // 32
    #pragma unroll 1
    for (int s = 0; s < NS; s++) {
        CP_WAIT1();
        __syncthreads();
        const uint32_t aA = sbase + (uint32_t)(s % 3) * DN_STAGE;
        const float* Bp = (const float*)(smem + (s % 3) * DN_STAGE + 16384);
        #pragma unroll
        for (int kk = 0; kk < 4; kk++) {
            uint32_t af[4][4];
            #pragma unroll
            for (int m2 = 0; m2 < 4; m2++)
                ldsm4(af[m2], aA + SWZ((mbase + m2 * 16 + (blk & 1) * 8 + r) * 128 + kk * 32 + (blk >> 1) * 16));
            uint32_t b0[4], b1[4];
            #pragma unroll
            for (int p = 0; p < 4; p++) {
                int n = nbase + p * 8 + nq;
                int k = kk * 8 + kb;
                b0[p] = f2tf32(Bp[k * DN_BROW + n]);
                b1[p] = f2tf32(Bp[(k + 4) * DN_BROW + n]);
            }
            #pragma unroll
            for (int m2 = 0; m2 < 4; m2++)
                #pragma unroll
                for (int p = 0; p < 4; p++)
                    mma8(acc[m2][p], af[m2], b0[p], b1[p]);
        }
        if (s + 2 < NS) issue(s + 2);
        CP_COMMIT();
    }

    const int g = lane >> 2, t4 = lane & 3;
    float* ob = out + (size_t)(e * TPE + mt * 128) * DIM + nt * 128;
    #pragma unroll
    for (int m2 = 0; m2 < 4; m2++) {
        #pragma unroll
        for (int p = 0; p < 4; p++) {
            int row = mbase + m2 * 16 + g;
            int col = nbase + p * 8 + 2 * t4;
            float* r0 = ob + (size_t)row * DIM + col;
            float* r1 = r0 + 8 * DIM;
            *(float2*)r0 = make_float2(acc[m2][p][0], acc[m2][p][1]);
            *(float2*)r1 = make_float2(acc[m2][p][2], acc[m2][p][3]);
        }
    }
}

// ======================================================================
extern "C" void kernel_launch(void* const* d_in, const int* in_sizes, int n_in,
                              void* d_out, int out_size)
{
    (void)in_sizes; (void)n_in; (void)out_size;
    const float* x  = (const float*)d_in[0];
    const float* w1 = (const float*)d_in[1];
    const float* w2 = (const float*)d_in[2];
    const float* w3 = (const float*)d_in[3];
    float* out = (float*)d_out;

    static bool attr_set = false;
    if (!attr_set) {
        cudaFuncSetAttribute(moe_up_kernel,   cudaFuncAttributeMaxDynamicSharedMemorySize, UP_SMEM);
        cudaFuncSetAttribute(moe_down_kernel, cudaFuncAttributeMaxDynamicSharedMemorySize, DN_SMEM);
        attr_set = true;
    }

    preround_kernel<<<2048, 256>>>(x);
    moe_up_kernel<<<NEXP * 32, 256, UP_SMEM>>>(w1, w3);
    moe_down_kernel<<<NEXP * 32, 256, DN_SMEM>>>(w2, out);
}

// round 5
// speedup vs baseline: 1.0558x; 1.0558x over previous
#include <cuda_runtime.h>
#include <cuda_bf16.h>
#include <cstdint>

// ---------------- problem constants ----------------
#define NEXP 64
#define DIM  2048
#define HID  1024
#define TOK  16384
#define TPE  256

// scratch: SwiGLU intermediate h (tf32-rounded) + pre-rounded X
__device__ float g_h[(size_t)TOK * HID];
__device__ float g_x[(size_t)TOK * DIM];

// ---------------- helpers ----------------
__device__ __forceinline__ uint32_t smem_u32(const void* p) {
    uint32_t a;
    asm("{ .reg .u64 t; cvta.to.shared.u64 t, %1; cvt.u32.u64 %0, t; }" : "=r"(a) : "l"(p));
    return a;
}
__device__ __forceinline__ uint32_t f2tf32(float x) {
    uint32_t r;
    asm("cvt.rna.tf32.f32 %0, %1;" : "=r"(r) : "f"(x));
    return r;
}

#define SWZ(x) ((x) ^ (((x) >> 3) & 0x70))

__device__ __forceinline__ void cp16(uint32_t dst, const void* src) {
    asm volatile("cp.async.cg.shared.global [%0], [%1], 16;" :: "r"(dst), "l"(src));
}
#define CP_COMMIT() asm volatile("cp.async.commit_group;" ::: "memory")
#define CP_WAIT2()  asm volatile("cp.async.wait_group 2;" ::: "memory")

__device__ __forceinline__ void ldsm4(uint32_t* f, uint32_t addr) {
    asm volatile("ldmatrix.sync.aligned.m8n8.x4.shared.b16 {%0,%1,%2,%3}, [%4];"
                 : "=r"(f[0]), "=r"(f[1]), "=r"(f[2]), "=r"(f[3]) : "r"(addr));
}

__device__ __forceinline__ void mma8(float* d, const uint32_t* a, uint32_t b0, uint32_t b1) {
    asm volatile("mma.sync.aligned.m16n8k8.row.col.f32.tf32.tf32.f32 "
                 "{%0,%1,%2,%3},{%4,%5,%6,%7},{%8,%9},{%0,%1,%2,%3};"
                 : "+f"(d[0]), "+f"(d[1]), "+f"(d[2]), "+f"(d[3])
                 : "r"(a[0]), "r"(a[1]), "r"(a[2]), "r"(a[3]), "r"(b0), "r"(b1));
}

__device__ __forceinline__ float silu(float v) {
    return v / (1.0f + __expf(-v));
}

// ---------------- smem layout ----------------
// A tile: 256 rows x 128B (SW128) = 32768
// DOWN B: [k32][n128] rows padded to 544B = 17408  -> stage 50176, 4 stages
#define DN_BROW   136
#define DN_STAGE  50176
#define DN_SMEM   (4 * DN_STAGE)     // 200704
// UP B1/B3: [k32][n64] rows padded to 288B = 9216 each -> stage 51200, 4 stages
#define UP_BROW   72
#define UP_B1OFF  32768
#define UP_B3OFF  41984
#define UP_STAGE  51200
#define UP_SMEM   (4 * UP_STAGE)     // 204800

// ======================================================================
// Kernel 0: pre-round X to tf32 (HW truncation of rna-rounded value = identity)
// ======================================================================
__global__ __launch_bounds__(256)
void preround_kernel(const float* __restrict__ x)
{
    size_t i = (size_t)(blockIdx.x * 256 + threadIdx.x);
    size_t stride = (size_t)gridDim.x * 256;
    const size_t n4 = (size_t)TOK * DIM / 4;
    float4* dst = (float4*)g_x;
    const float4* src = (const float4*)x;
    for (; i < n4; i += stride) {
        float4 v = src[i];
        float4 t;
        t.x = __uint_as_float(f2tf32(v.x));
        t.y = __uint_as_float(f2tf32(v.y));
        t.z = __uint_as_float(f2tf32(v.z));
        t.w = __uint_as_float(f2tf32(v.w));
        dst[i] = t;
    }
}

// ======================================================================
// Kernel A: h = silu(X@W1) * (X@W3). CTA: 256m x 64n (W1+W3), 512 thr.
// Warp grid 4m x 4n; warp tile 64m x 16n per GEMM. grid = 64 * 16 = 1024.
// ======================================================================
__global__ __launch_bounds__(512, 1)
void moe_up_kernel(const float* __restrict__ w1,
                   const float* __restrict__ w3)
{
    extern __shared__ __align__(1024) char smem[];
    const uint32_t sbase = smem_u32(smem);
    const int tid  = threadIdx.x;
    const int lane = tid & 31;
    const int wid  = tid >> 5;
    const int bid  = blockIdx.x;
    const int e    = bid >> 4;
    const int nt   = bid & 15;       // 16 tiles of 64

    const float* xb  = g_x + (size_t)(e * TPE) * DIM;
    const float* w1b = w1 + (size_t)e * DIM * HID + nt * 64;
    const float* w3b = w3 + (size_t)e * DIM * HID + nt * 64;

    const int wm = wid >> 2, wn = wid & 3;
    const int mbase = wm * 64, nbase = wn * 16;
    const int blk = lane >> 3, r = lane & 7;

    const int am = tid >> 3, aq = tid & 7;   // A rows am + j*64
    const int bk = tid >> 4, bq = tid & 15;  // B row bk, chunk bq

    auto issue = [&](int s) {
        const uint32_t buf = sbase + (uint32_t)(s & 3) * UP_STAGE;
        const int k0 = s * 32;
        #pragma unroll
        for (int j = 0; j < 4; j++) {
            int m = am + j * 64;
            cp16(buf + SWZ(m * 128 + aq * 16), xb + (size_t)m * DIM + k0 + aq * 4);
        }
        cp16(buf + UP_B1OFF + bk * 288 + bq * 16, w1b + (size_t)(k0 + bk) * HID + bq * 4);
        cp16(buf + UP_B3OFF + bk * 288 + bq * 16, w3b + (size_t)(k0 + bk) * HID + bq * 4);
    };

    float acc1[4][2][4], acc3[4][2][4];
    #pragma unroll
    for (int i = 0; i < 4; i++)
        #pragma unroll
        for (int j = 0; j < 2; j++)
            #pragma unroll
            for (int k = 0; k < 4; k++) { acc1[i][j][k] = 0.f; acc3[i][j][k] = 0.f; }

    issue(0); CP_COMMIT();
    issue(1); CP_COMMIT();
    issue(2); CP_COMMIT();

    const int kb = lane & 3, nq = lane >> 2;
    const int NS = DIM / 32;   // 64
    #pragma unroll 1
    for (int s = 0; s < NS; s++) {
        CP_WAIT2();
        __syncthreads();
        const uint32_t aA = sbase + (uint32_t)(s & 3) * UP_STAGE;
        const float* B1p = (const float*)(smem + (size_t)(s & 3) * UP_STAGE + UP_B1OFF);
        const float* B3p = (const float*)(smem + (size_t)(s & 3) * UP_STAGE + UP_B3OFF);
        #pragma unroll
        for (int kk = 0; kk < 4; kk++) {
            uint32_t af[4][4];
            #pragma unroll
            for (int m2 = 0; m2 < 4; m2++)
                ldsm4(af[m2], aA + SWZ((mbase + m2 * 16 + (blk & 1) * 8 + r) * 128 + kk * 32 + (blk >> 1) * 16));
            uint32_t b10[2], b11[2], b30[2], b31[2];
            #pragma unroll
            for (int p = 0; p < 2; p++) {
                int n = nbase + p * 8 + nq;
                int k = kk * 8 + kb;
                b10[p] = f2tf32(B1p[k * UP_BROW + n]);
                b11[p] = f2tf32(B1p[(k + 4) * UP_BROW + n]);
                b30[p] = f2tf32(B3p[k * UP_BROW + n]);
                b31[p] = f2tf32(B3p[(k + 4) * UP_BROW + n]);
            }
            #pragma unroll
            for (int m2 = 0; m2 < 4; m2++)
                #pragma unroll
                for (int p = 0; p < 2; p++) {
                    mma8(acc1[m2][p], af[m2], b10[p], b11[p]);
                    mma8(acc3[m2][p], af[m2], b30[p], b31[p]);
                }
        }
        if (s + 3 < NS) issue(s + 3);
        CP_COMMIT();
    }

    // fused SwiGLU epilogue -> g_h (tf32-rounded: identity under later truncation)
    const int g = lane >> 2, t4 = lane & 3;
    float* hb = g_h + (size_t)(e * TPE) * HID + nt * 64;
    #pragma unroll
    for (int m2 = 0; m2 < 4; m2++) {
        #pragma unroll
        for (int p = 0; p < 2; p++) {
            int row = mbase + m2 * 16 + g;
            int col = nbase + p * 8 + 2 * t4;
            float* r0 = hb + (size_t)row * HID + col;
            float* r1 = r0 + 8 * HID;
            *(float2*)r0 = make_float2(
                __uint_as_float(f2tf32(silu(acc1[m2][p][0]) * acc3[m2][p][0])),
                __uint_as_float(f2tf32(silu(acc1[m2][p][1]) * acc3[m2][p][1])));
            *(float2*)r1 = make_float2(
                __uint_as_float(f2tf32(silu(acc1[m2][p][2]) * acc3[m2][p][2])),
                __uint_as_float(f2tf32(silu(acc1[m2][p][3]) * acc3[m2][p][3])));
        }
    }
}

// ======================================================================
// Kernel B: out = h @ W2. CTA: 256m x 128n, 512 thr.
// Warp grid 4m x 4n; warp tile 64m x 32n. grid = 64 * 16 = 1024.
// ======================================================================
__global__ __launch_bounds__(512, 1)
void moe_down_kernel(const float* __restrict__ w2, float* __restrict__ out)
{
    extern __shared__ __align__(1024) char smem[];
    const uint32_t sbase = smem_u32(smem);
    const int tid  = threadIdx.x;
    const int lane = tid & 31;
    const int wid  = tid >> 5;
    const int bid  = blockIdx.x;
    const int e    = bid >> 4;
    const int nt   = bid & 15;       // 16 tiles of 128

    const float* hb  = g_h + (size_t)(e * TPE) * HID;
    const float* w2b = w2 + (size_t)e * HID * DIM + nt * 128;

    const int wm = wid >> 2, wn = wid & 3;
    const int mbase = wm * 64, nbase = wn * 32;
    const int blk = lane >> 3, r = lane & 7;

    const int am = tid >> 3, aq = tid & 7;   // A rows am + j*64
    const int bk = tid >> 5, bq = tid & 31;  // B rows bk + j*16, chunk bq

    auto issue = [&](int s) {
        const uint32_t buf = sbase + (uint32_t)(s & 3) * DN_STAGE;
        const int k0 = s * 32;
        #pragma unroll
        for (int j = 0; j < 4; j++) {
            int m = am + j * 64;
            cp16(buf + SWZ(m * 128 + aq * 16), hb + (size_t)m * HID + k0 + aq * 4);
        }
        #pragma unroll
        for (int j = 0; j < 2; j++) {
            int k = bk + j * 16;
            cp16(buf + 32768 + k * 544 + bq * 16, w2b + (size_t)(k0 + k) * DIM + bq * 4);
        }
    };

    float acc[4][4][4];
    #pragma unroll
    for (int i = 0; i < 4; i++)
        #pragma unroll
        for (int j = 0; j < 4; j++)
            #pragma unroll
            for (int k = 0; k < 4; k++) acc[i][j][k] = 0.f;

    issue(0); CP_COMMIT();
    issue(1); CP_COMMIT();
    issue(2); CP_COMMIT();

    const int kb = lane & 3, nq = lane >> 2;
    const int NS = HID / 32;   // 32
    #pragma unroll 1
    for (int s = 0; s < NS; s++) {
        CP_WAIT2();
        __syncthreads();
        const uint32_t aA = sbase + (uint32_t)(s & 3) * DN_STAGE;
        const float* Bp = (const float*)(smem + (size_t)(s & 3) * DN_STAGE + 32768);
        #pragma unroll
        for (int kk = 0; kk < 4; kk++) {
            uint32_t af[4][4];
            #pragma unroll
            for (int m2 = 0; m2 < 4; m2++)
                ldsm4(af[m2], aA + SWZ((mbase + m2 * 16 + (blk & 1) * 8 + r) * 128 + kk * 32 + (blk >> 1) * 16));
            uint32_t b0[4], b1[4];
            #pragma unroll
            for (int p = 0; p < 4; p++) {
                int n = nbase + p * 8 + nq;
                int k = kk * 8 + kb;
                b0[p] = f2tf32(Bp[k * DN_BROW + n]);
                b1[p] = f2tf32(Bp[(k + 4) * DN_BROW + n]);
            }
            #pragma unroll
            for (int m2 = 0; m2 < 4; m2++)
                #pragma unroll
                for (int p = 0; p < 4; p++)
                    mma8(acc[m2][p], af[m2], b0[p], b1[p]);
        }
        if (s + 3 < NS) issue(s + 3);
        CP_COMMIT();
    }

    const int g = lane >> 2, t4 = lane & 3;
    float* ob = out + (size_t)(e * TPE) * DIM + nt * 128;
    #pragma unroll
    for (int m2 = 0; m2 < 4; m2++) {
        #pragma unroll
        for (int p = 0; p < 4; p++) {
            int row = mbase + m2 * 16 + g;
            int col = nbase + p * 8 + 2 * t4;
            float* r0 = ob + (size_t)row * DIM + col;
            float* r1 = r0 + 8 * DIM;
            *(float2*)r0 = make_float2(acc[m2][p][0], acc[m2][p][1]);
            *(float2*)r1 = make_float2(acc[m2][p][2], acc[m2][p][3]);
        }
    }
}

// ======================================================================
extern "C" void kernel_launch(void* const* d_in, const int* in_sizes, int n_in,
                              void* d_out, int out_size)
{
    (void)in_sizes; (void)n_in; (void)out_size;
    const float* x  = (const float*)d_in[0];
    const float* w1 = (const float*)d_in[1];
    const float* w2 = (const float*)d_in[2];
    const float* w3 = (const float*)d_in[3];
    float* out = (float*)d_out;

    static bool attr_set = false;
    if (!attr_set) {
        cudaFuncSetAttribute(moe_up_kernel,   cudaFuncAttributeMaxDynamicSharedMemorySize, UP_SMEM);
        cudaFuncSetAttribute(moe_down_kernel, cudaFuncAttributeMaxDynamicSharedMemorySize, DN_SMEM);
        attr_set = true;
    }

    preround_kernel<<<2048, 256>>>(x);
    moe_up_kernel<<<NEXP * 16, 512, UP_SMEM>>>(w1, w3);
    moe_down_kernel<<<NEXP * 16, 512, DN_SMEM>>>(w2, out);
}

// round 6
// speedup vs baseline: 1.1166x; 1.0576x over previous
#include <cuda_runtime.h>
#include <cuda_bf16.h>
#include <cstdint>

// ---------------- problem constants ----------------
#define NEXP 64
#define DIM  2048
#define HID  1024
#define TOK  16384
#define TPE  256

// scratch: SwiGLU intermediate h (tf32-rounded) + pre-rounded X
__device__ float g_h[(size_t)TOK * HID];
__device__ float g_x[(size_t)TOK * DIM];

// ---------------- helpers ----------------
__device__ __forceinline__ uint32_t smem_u32(const void* p) {
    uint32_t a;
    asm("{ .reg .u64 t; cvta.to.shared.u64 t, %1; cvt.u32.u64 %0, t; }" : "=r"(a) : "l"(p));
    return a;
}
__device__ __forceinline__ uint32_t f2tf32(float x) {
    uint32_t r;
    asm("cvt.rna.tf32.f32 %0, %1;" : "=r"(r) : "f"(x));
    return r;
}

#define SWZ(x) ((x) ^ (((x) >> 3) & 0x70))

__device__ __forceinline__ void cp16(uint32_t dst, const void* src) {
    asm volatile("cp.async.cg.shared.global [%0], [%1], 16;" :: "r"(dst), "l"(src));
}
#define CP_COMMIT() asm volatile("cp.async.commit_group;" ::: "memory")
#define CP_WAIT2()  asm volatile("cp.async.wait_group 2;" ::: "memory")

__device__ __forceinline__ void ldsm4(uint32_t* f, uint32_t addr) {
    asm volatile("ldmatrix.sync.aligned.m8n8.x4.shared.b16 {%0,%1,%2,%3}, [%4];"
                 : "=r"(f[0]), "=r"(f[1]), "=r"(f[2]), "=r"(f[3]) : "r"(addr));
}

__device__ __forceinline__ void mma8(float* d, const uint32_t* a, uint32_t b0, uint32_t b1) {
    asm volatile("mma.sync.aligned.m16n8k8.row.col.f32.tf32.tf32.f32 "
                 "{%0,%1,%2,%3},{%4,%5,%6,%7},{%8,%9},{%0,%1,%2,%3};"
                 : "+f"(d[0]), "+f"(d[1]), "+f"(d[2]), "+f"(d[3])
                 : "r"(a[0]), "r"(a[1]), "r"(a[2]), "r"(a[3]), "r"(b0), "r"(b1));
}

__device__ __forceinline__ float silu(float v) {
    return v / (1.0f + __expf(-v));
}

// ---------------- smem layout ----------------
// A stages: 4 x 32768 (256 rows x 128B, SW128) at offset 0.
// B stages: n-major, row pitch 144B (conflict-free for STS.128 and ldmatrix).
// DOWN: B = 128 rows x 144B = 18432/stage at offset 131072. total 204800.
// UP:   B1 (64x144=9216) + B3 (9216) = 18432/stage at 131072. total 204800.
#define ABUF_SZ  32768
#define BOFF     131072
#define DN_BSTG  18432
#define UP_BSTG  18432
#define SMEM_TOT 204800

// ======================================================================
// Kernel 0: pre-round X to tf32 (HW truncation of rna-rounded value = identity)
// ======================================================================
__global__ __launch_bounds__(256)
void preround_kernel(const float* __restrict__ x)
{
    size_t i = (size_t)(blockIdx.x * 256 + threadIdx.x);
    size_t stride = (size_t)gridDim.x * 256;
    const size_t n4 = (size_t)TOK * DIM / 4;
    float4* dst = (float4*)g_x;
    const float4* src = (const float4*)x;
    for (; i < n4; i += stride) {
        float4 v = src[i];
        float4 t;
        t.x = __uint_as_float(f2tf32(v.x));
        t.y = __uint_as_float(f2tf32(v.y));
        t.z = __uint_as_float(f2tf32(v.z));
        t.w = __uint_as_float(f2tf32(v.w));
        dst[i] = t;
    }
}

// ======================================================================
// Kernel A: h = silu(X@W1) * (X@W3). CTA: 256m x 64n (W1+W3), 512 thr.
// Warp grid 4m x 4n; warp tile 64m x 16n per GEMM. grid = 64 * 16 = 1024.
// B staged n-major via LDG->cvt->STS (transpose), consumed by ldmatrix.
// ======================================================================
__global__ __launch_bounds__(512, 1)
void moe_up_kernel(const float* __restrict__ w1,
                   const float* __restrict__ w3)
{
    extern __shared__ __align__(1024) char smem[];
    const uint32_t sbase = smem_u32(smem);
    const int tid  = threadIdx.x;
    const int lane = tid & 31;
    const int wid  = tid >> 5;
    const int bid  = blockIdx.x;
    const int e    = bid >> 4;
    const int nt   = bid & 15;       // 16 tiles of 64

    const float* xb  = g_x + (size_t)(e * TPE) * DIM;
    const float* w1b = w1 + (size_t)e * DIM * HID + nt * 64;
    const float* w3b = w3 + (size_t)e * DIM * HID + nt * 64;

    const int wm = wid >> 2, wn = wid & 3;
    const int mbase = wm * 64, nbase = wn * 16;
    const int blk = lane >> 3, r = lane & 7;

    const int am = tid >> 3, aq = tid & 7;   // A rows am + j*64
    const int nb = tid & 63, kset = tid >> 6; // B: n row, k-quad (0..7)

    auto cpA = [&](int s) {
        const uint32_t buf = sbase + (uint32_t)(s & 3) * ABUF_SZ;
        const int k0 = s * 32;
        #pragma unroll
        for (int j = 0; j < 4; j++) {
            int m = am + j * 64;
            cp16(buf + SWZ(m * 128 + aq * 16), xb + (size_t)m * DIM + k0 + aq * 4);
        }
    };
    float4 r1, r3;
    auto ldgB = [&](int s) {
        const int k = s * 32 + kset * 4;
        const float* p1 = w1b + (size_t)k * HID + nb;
        r1 = make_float4(p1[0], p1[HID], p1[2 * HID], p1[3 * HID]);
        const float* p3 = w3b + (size_t)k * HID + nb;
        r3 = make_float4(p3[0], p3[HID], p3[2 * HID], p3[3 * HID]);
    };
    auto stsB = [&](int s) {
        char* buf = smem + BOFF + (size_t)(s & 3) * UP_BSTG;
        uint4 t1 = { f2tf32(r1.x), f2tf32(r1.y), f2tf32(r1.z), f2tf32(r1.w) };
        *(uint4*)(buf + nb * 144 + kset * 16) = t1;
        uint4 t3 = { f2tf32(r3.x), f2tf32(r3.y), f2tf32(r3.z), f2tf32(r3.w) };
        *(uint4*)(buf + 9216 + nb * 144 + kset * 16) = t3;
    };

    float acc1[4][2][4], acc3[4][2][4];
    #pragma unroll
    for (int i = 0; i < 4; i++)
        #pragma unroll
        for (int j = 0; j < 2; j++)
            #pragma unroll
            for (int k = 0; k < 4; k++) { acc1[i][j][k] = 0.f; acc3[i][j][k] = 0.f; }

    // prologue
    ldgB(0); stsB(0);
    ldgB(1); stsB(1);
    ldgB(2);                       // held in regs, stored in body s=0
    cpA(0); CP_COMMIT();
    cpA(1); CP_COMMIT();
    cpA(2); CP_COMMIT();

    // per-lane B ldmatrix row base (n-major, pitch 144, mats: (grp,chk) = (q>>1, q&1))
    const int q = lane >> 3, rr = lane & 7;
    const uint32_t brel = (uint32_t)(nbase + (q >> 1) * 8 + rr) * 144 + (uint32_t)(q & 1) * 16;

    const int NS = DIM / 32;   // 64
    #pragma unroll 1
    for (int s = 0; s < NS; s++) {
        CP_WAIT2();
        __syncthreads();
        const uint32_t aA = sbase + (uint32_t)(s & 3) * ABUF_SZ;
        const uint32_t aB1 = sbase + BOFF + (uint32_t)(s & 3) * UP_BSTG + brel;
        const uint32_t aB3 = aB1 + 9216;
        #pragma unroll
        for (int kk = 0; kk < 4; kk++) {
            uint32_t af[4][4];
            #pragma unroll
            for (int m2 = 0; m2 < 4; m2++)
                ldsm4(af[m2], aA + SWZ((mbase + m2 * 16 + (blk & 1) * 8 + r) * 128 + kk * 32 + (blk >> 1) * 16));
            uint32_t bf1[4], bf3[4];
            ldsm4(bf1, aB1 + kk * 32);
            ldsm4(bf3, aB3 + kk * 32);
            #pragma unroll
            for (int m2 = 0; m2 < 4; m2++)
                #pragma unroll
                for (int p = 0; p < 2; p++) {
                    mma8(acc1[m2][p], af[m2], bf1[p * 2], bf1[p * 2 + 1]);
                    mma8(acc3[m2][p], af[m2], bf3[p * 2], bf3[p * 2 + 1]);
                }
        }
        if (s + 2 < NS) stsB(s + 2);
        if (s + 3 < NS) { ldgB(s + 3); cpA(s + 3); }
        CP_COMMIT();
    }

    // fused SwiGLU epilogue -> g_h (tf32-rounded: identity under later truncation)
    const int g = lane >> 2, t4 = lane & 3;
    float* hb = g_h + (size_t)(e * TPE) * HID + nt * 64;
    #pragma unroll
    for (int m2 = 0; m2 < 4; m2++) {
        #pragma unroll
        for (int p = 0; p < 2; p++) {
            int row = mbase + m2 * 16 + g;
            int col = nbase + p * 8 + 2 * t4;
            float* r0 = hb + (size_t)row * HID + col;
            float* r1p = r0 + 8 * HID;
            *(float2*)r0 = make_float2(
                __uint_as_float(f2tf32(silu(acc1[m2][p][0]) * acc3[m2][p][0])),
                __uint_as_float(f2tf32(silu(acc1[m2][p][1]) * acc3[m2][p][1])));
            *(float2*)r1p = make_float2(
                __uint_as_float(f2tf32(silu(acc1[m2][p][2]) * acc3[m2][p][2])),
                __uint_as_float(f2tf32(silu(acc1[m2][p][3]) * acc3[m2][p][3])));
        }
    }
}

// ======================================================================
// Kernel B: out = h @ W2. CTA: 256m x 128n, 512 thr.
// Warp grid 4m x 4n; warp tile 64m x 32n. grid = 64 * 16 = 1024.
// ======================================================================
__global__ __launch_bounds__(512, 1)
void moe_down_kernel(const float* __restrict__ w2, float* __restrict__ out)
{
    extern __shared__ __align__(1024) char smem[];
    const uint32_t sbase = smem_u32(smem);
    const int tid  = threadIdx.x;
    const int lane = tid & 31;
    const int wid  = tid >> 5;
    const int bid  = blockIdx.x;
    const int e    = bid >> 4;
    const int nt   = bid & 15;       // 16 tiles of 128

    const float* hb  = g_h + (size_t)(e * TPE) * HID;
    const float* w2b = w2 + (size_t)e * HID * DIM + nt * 128;

    const int wm = wid >> 2, wn = wid & 3;
    const int mbase = wm * 64, nbase = wn * 32;
    const int blk = lane >> 3, r = lane & 7;

    const int am = tid >> 3, aq = tid & 7;     // A rows am + j*64
    const int nb = tid & 127, kset = tid >> 7; // B: n row, k-quad base (0..3), +4 for j=1

    auto cpA = [&](int s) {
        const uint32_t buf = sbase + (uint32_t)(s & 3) * ABUF_SZ;
        const int k0 = s * 32;
        #pragma unroll
        for (int j = 0; j < 4; j++) {
            int m = am + j * 64;
            cp16(buf + SWZ(m * 128 + aq * 16), hb + (size_t)m * HID + k0 + aq * 4);
        }
    };
    float4 rB[2];
    auto ldgB = [&](int s) {
        #pragma unroll
        for (int j = 0; j < 2; j++) {
            const int k = s * 32 + (kset + j * 4) * 4;
            const float* p = w2b + (size_t)k * DIM + nb;
            rB[j] = make_float4(p[0], p[DIM], p[2 * DIM], p[3 * DIM]);
        }
    };
    auto stsB = [&](int s) {
        char* buf = smem + BOFF + (size_t)(s & 3) * DN_BSTG;
        #pragma unroll
        for (int j = 0; j < 2; j++) {
            uint4 t = { f2tf32(rB[j].x), f2tf32(rB[j].y), f2tf32(rB[j].z), f2tf32(rB[j].w) };
            *(uint4*)(buf + nb * 144 + (kset + j * 4) * 16) = t;
        }
    };

    float acc[4][4][4];
    #pragma unroll
    for (int i = 0; i < 4; i++)
        #pragma unroll
        for (int j = 0; j < 4; j++)
            #pragma unroll
            for (int k = 0; k < 4; k++) acc[i][j][k] = 0.f;

    // prologue
    ldgB(0); stsB(0);
    ldgB(1); stsB(1);
    ldgB(2);
    cpA(0); CP_COMMIT();
    cpA(1); CP_COMMIT();
    cpA(2); CP_COMMIT();

    const int q = lane >> 3, rr = lane & 7;
    const uint32_t brel = (uint32_t)(nbase + (q >> 1) * 8 + rr) * 144 + (uint32_t)(q & 1) * 16;

    const int NS = HID / 32;   // 32
    #pragma unroll 1
    for (int s = 0; s < NS; s++) {
        CP_WAIT2();
        __syncthreads();
        const uint32_t aA = sbase + (uint32_t)(s & 3) * ABUF_SZ;
        const uint32_t aB = sbase + BOFF + (uint32_t)(s & 3) * DN_BSTG + brel;
        #pragma unroll
        for (int kk = 0; kk < 4; kk++) {
            uint32_t af[4][4];
            #pragma unroll
            for (int m2 = 0; m2 < 4; m2++)
                ldsm4(af[m2], aA + SWZ((mbase + m2 * 16 + (blk & 1) * 8 + r) * 128 + kk * 32 + (blk >> 1) * 16));
            uint32_t bf[2][4];
            ldsm4(bf[0], aB + kk * 32);            // n rows nbase..nbase+15
            ldsm4(bf[1], aB + 2304 + kk * 32);     // n rows nbase+16..nbase+31 (16*144)
            #pragma unroll
            for (int m2 = 0; m2 < 4; m2++)
                #pragma unroll
                for (int p = 0; p < 4; p++)
                    mma8(acc[m2][p], af[m2], bf[p >> 1][(p & 1) * 2], bf[p >> 1][(p & 1) * 2 + 1]);
        }
        if (s + 2 < NS) stsB(s + 2);
        if (s + 3 < NS) { ldgB(s + 3); cpA(s + 3); }
        CP_COMMIT();
    }

    const int g = lane >> 2, t4 = lane & 3;
    float* ob = out + (size_t)(e * TPE) * DIM + nt * 128;
    #pragma unroll
    for (int m2 = 0; m2 < 4; m2++) {
        #pragma unroll
        for (int p = 0; p < 4; p++) {
            int row = mbase + m2 * 16 + g;
            int col = nbase + p * 8 + 2 * t4;
            float* r0 = ob + (size_t)row * DIM + col;
            float* r1p = r0 + 8 * DIM;
            *(float2*)r0 = make_float2(acc[m2][p][0], acc[m2][p][1]);
            *(float2*)r1p = make_float2(acc[m2][p][2], acc[m2][p][3]);
        }
    }
}

// ======================================================================
extern "C" void kernel_launch(void* const* d_in, const int* in_sizes, int n_in,
                              void* d_out, int out_size)
{
    (void)in_sizes; (void)n_in; (void)out_size;
    const float* x  = (const float*)d_in[0];
    const float* w1 = (const float*)d_in[1];
    const float* w2 = (const float*)d_in[2];
    const float* w3 = (const float*)d_in[3];
    float* out = (float*)d_out;

    static bool attr_set = false;
    if (!attr_set) {
        cudaFuncSetAttribute(moe_up_kernel,   cudaFuncAttributeMaxDynamicSharedMemorySize, SMEM_TOT);
        cudaFuncSetAttribute(moe_down_kernel, cudaFuncAttributeMaxDynamicSharedMemorySize, SMEM_TOT);
        attr_set = true;
    }

    preround_kernel<<<2048, 256>>>(x);
    moe_up_kernel<<<NEXP * 16, 512, SMEM_TOT>>>(w1, w3);
    moe_down_kernel<<<NEXP * 16, 512, SMEM_TOT>>>(w2, out);
}

// round 7
// speedup vs baseline: 1.4185x; 1.2705x over previous
#include <cuda_runtime.h>
#include <cuda_fp16.h>
#include <cstdint>

// ---------------- problem constants ----------------
#define NEXP 64
#define DIM  2048
#define HID  1024
#define TOK  16384
#define TPE  256

// scratch: fp16 SwiGLU intermediate + fp16 pre-converted X
__device__ __half g_h[(size_t)TOK * HID];
__device__ __half g_x[(size_t)TOK * DIM];

// ---------------- helpers ----------------
__device__ __forceinline__ uint32_t smem_u32(const void* p) {
    uint32_t a;
    asm("{ .reg .u64 t; cvta.to.shared.u64 t, %1; cvt.u32.u64 %0, t; }" : "=r"(a) : "l"(p));
    return a;
}
// pack two floats to fp16x2 (round-to-nearest-even)
__device__ __forceinline__ uint32_t pkh2(float lo, float hi) {
    uint32_t r;
    asm("cvt.rn.f16x2.f32 %0, %1, %2;" : "=r"(r) : "f"(hi), "f"(lo));
    return r;
}

#define SWZ(x) ((x) ^ (((x) >> 3) & 0x70))

__device__ __forceinline__ void cp16(uint32_t dst, const void* src) {
    asm volatile("cp.async.cg.shared.global [%0], [%1], 16;" :: "r"(dst), "l"(src));
}
#define CP_COMMIT() asm volatile("cp.async.commit_group;" ::: "memory")
#define CP_WAIT2()  asm volatile("cp.async.wait_group 2;" ::: "memory")

__device__ __forceinline__ void ldsm4(uint32_t* f, uint32_t addr) {
    asm volatile("ldmatrix.sync.aligned.m8n8.x4.shared.b16 {%0,%1,%2,%3}, [%4];"
                 : "=r"(f[0]), "=r"(f[1]), "=r"(f[2]), "=r"(f[3]) : "r"(addr));
}

// mma m16n8k16 fp16 -> fp32 accum
__device__ __forceinline__ void mma16(float* d, const uint32_t* a, uint32_t b0, uint32_t b1) {
    asm volatile("mma.sync.aligned.m16n8k16.row.col.f32.f16.f16.f32 "
                 "{%0,%1,%2,%3},{%4,%5,%6,%7},{%8,%9},{%0,%1,%2,%3};"
                 : "+f"(d[0]), "+f"(d[1]), "+f"(d[2]), "+f"(d[3])
                 : "r"(a[0]), "r"(a[1]), "r"(a[2]), "r"(a[3]), "r"(b0), "r"(b1));
}

__device__ __forceinline__ float silu(float v) {
    return v / (1.0f + __expf(-v));
}

// ---------------- smem layout ----------------
// A stages: 4 x 32768B (256 rows x 128B = 64 fp16 k, SW128) at offset 0.
// B stages: n-major fp16, row pitch 144B (64 fp16 k + pad), at 131072.
// DOWN: 128 n-rows x 144B = 18432/stage. UP: B1(64x144) + B3 = 18432/stage.
#define ABUF_SZ  32768
#define BOFF     131072
#define BSTG     18432
#define SMEM_TOT 204800

// ======================================================================
// Kernel 0: convert X to fp16 once
// ======================================================================
__global__ __launch_bounds__(256)
void preconv_kernel(const float* __restrict__ x)
{
    size_t i = (size_t)(blockIdx.x * 256 + threadIdx.x);
    size_t stride = (size_t)gridDim.x * 256;
    const size_t n4 = (size_t)TOK * DIM / 4;
    uint2* dst = (uint2*)g_x;
    const float4* src = (const float4*)x;
    for (; i < n4; i += stride) {
        float4 v = src[i];
        dst[i] = make_uint2(pkh2(v.x, v.y), pkh2(v.z, v.w));
    }
}

// ======================================================================
// Kernel A: h = silu(X@W1) * (X@W3). CTA: 256m x 64n (W1+W3), 512 thr.
// Warp grid 4m x 4n; warp tile 64m x 16n per GEMM. grid = 64 * 16 = 1024.
// K-tile 64 (fp16). B staged n-major via LDG->cvt->STS, consumed by ldmatrix.
// ======================================================================
__global__ __launch_bounds__(512, 1)
void moe_up_kernel(const float* __restrict__ w1,
                   const float* __restrict__ w3)
{
    extern __shared__ __align__(1024) char smem[];
    const uint32_t sbase = smem_u32(smem);
    const int tid  = threadIdx.x;
    const int lane = tid & 31;
    const int wid  = tid >> 5;
    const int bid  = blockIdx.x;
    const int e    = bid >> 4;
    const int nt   = bid & 15;       // 16 tiles of 64

    const __half* xb = g_x + (size_t)(e * TPE) * DIM;
    const float* w1b = w1 + (size_t)e * DIM * HID + nt * 64;
    const float* w3b = w3 + (size_t)e * DIM * HID + nt * 64;

    const int wm = wid >> 2, wn = wid & 3;
    const int mbase = wm * 64, nbase = wn * 16;
    const int blk = lane >> 3, r = lane & 7;

    const int am = tid >> 3, aq = tid & 7;    // A rows am + j*64, 16B chunk aq
    const int nb = tid & 63, kq = tid >> 6;   // B: n row, k-oct (0..7)

    auto cpA = [&](int s) {
        const uint32_t buf = sbase + (uint32_t)(s & 3) * ABUF_SZ;
        const int k0 = s * 64;
        #pragma unroll
        for (int j = 0; j < 4; j++) {
            int m = am + j * 64;
            cp16(buf + SWZ(m * 128 + aq * 16), xb + (size_t)m * DIM + k0 + aq * 8);
        }
    };
    float v1[8], v3[8];
    auto ldgB = [&](int s) {
        const int k0 = s * 64 + kq * 8;
        #pragma unroll
        for (int t = 0; t < 8; t++) {
            v1[t] = w1b[(size_t)(k0 + t) * HID + nb];
            v3[t] = w3b[(size_t)(k0 + t) * HID + nb];
        }
    };
    auto stsB = [&](int s) {
        char* buf = smem + BOFF + (size_t)(s & 3) * BSTG;
        uint4 t1 = { pkh2(v1[0], v1[1]), pkh2(v1[2], v1[3]), pkh2(v1[4], v1[5]), pkh2(v1[6], v1[7]) };
        *(uint4*)(buf + nb * 144 + kq * 16) = t1;
        uint4 t3 = { pkh2(v3[0], v3[1]), pkh2(v3[2], v3[3]), pkh2(v3[4], v3[5]), pkh2(v3[6], v3[7]) };
        *(uint4*)(buf + 9216 + nb * 144 + kq * 16) = t3;
    };

    float acc1[4][2][4], acc3[4][2][4];
    #pragma unroll
    for (int i = 0; i < 4; i++)
        #pragma unroll
        for (int j = 0; j < 2; j++)
            #pragma unroll
            for (int k = 0; k < 4; k++) { acc1[i][j][k] = 0.f; acc3[i][j][k] = 0.f; }

    // prologue
    ldgB(0); stsB(0);
    ldgB(1); stsB(1);
    ldgB(2);
    cpA(0); CP_COMMIT();
    cpA(1); CP_COMMIT();
    cpA(2); CP_COMMIT();

    // B ldmatrix lane base: mats j=lane>>3: n += (j&1)*8, koff = (j>>1)*16B
    const int q = lane >> 3, rr = lane & 7;
    const uint32_t brel = (uint32_t)(nbase + (q & 1) * 8 + rr) * 144 + (uint32_t)(q >> 1) * 16;

    const int NS = DIM / 64;   // 32
    #pragma unroll 1
    for (int s = 0; s < NS; s++) {
        CP_WAIT2();
        __syncthreads();
        const uint32_t aA  = sbase + (uint32_t)(s & 3) * ABUF_SZ;
        const uint32_t aB1 = sbase + BOFF + (uint32_t)(s & 3) * BSTG + brel;
        const uint32_t aB3 = aB1 + 9216;
        #pragma unroll
        for (int kk = 0; kk < 4; kk++) {
            uint32_t af[4][4];
            #pragma unroll
            for (int m2 = 0; m2 < 4; m2++)
                ldsm4(af[m2], aA + SWZ((mbase + m2 * 16 + (blk & 1) * 8 + r) * 128 + kk * 32 + (blk >> 1) * 16));
            uint32_t bf1[4], bf3[4];
            ldsm4(bf1, aB1 + kk * 32);
            ldsm4(bf3, aB3 + kk * 32);
            #pragma unroll
            for (int m2 = 0; m2 < 4; m2++)
                #pragma unroll
                for (int p = 0; p < 2; p++) {
                    mma16(acc1[m2][p], af[m2], bf1[p], bf1[p + 2]);
                    mma16(acc3[m2][p], af[m2], bf3[p], bf3[p + 2]);
                }
        }
        if (s + 2 < NS) stsB(s + 2);
        if (s + 3 < NS) { ldgB(s + 3); cpA(s + 3); }
        CP_COMMIT();
    }

    // fused SwiGLU epilogue -> g_h (fp16)
    const int g = lane >> 2, t4 = lane & 3;
    __half* hb = g_h + (size_t)(e * TPE) * HID + nt * 64;
    #pragma unroll
    for (int m2 = 0; m2 < 4; m2++) {
        #pragma unroll
        for (int p = 0; p < 2; p++) {
            int row = mbase + m2 * 16 + g;
            int col = nbase + p * 8 + 2 * t4;
            *(uint32_t*)(hb + (size_t)row * HID + col) =
                pkh2(silu(acc1[m2][p][0]) * acc3[m2][p][0],
                     silu(acc1[m2][p][1]) * acc3[m2][p][1]);
            *(uint32_t*)(hb + (size_t)(row + 8) * HID + col) =
                pkh2(silu(acc1[m2][p][2]) * acc3[m2][p][2],
                     silu(acc1[m2][p][3]) * acc3[m2][p][3]);
        }
    }
}

// ======================================================================
// Kernel B: out = h @ W2. CTA: 256m x 128n, 512 thr.
// Warp grid 4m x 4n; warp tile 64m x 32n. K-tile 64. grid = 1024.
// ======================================================================
__global__ __launch_bounds__(512, 1)
void moe_down_kernel(const float* __restrict__ w2, float* __restrict__ out)
{
    extern __shared__ __align__(1024) char smem[];
    const uint32_t sbase = smem_u32(smem);
    const int tid  = threadIdx.x;
    const int lane = tid & 31;
    const int wid  = tid >> 5;
    const int bid  = blockIdx.x;
    const int e    = bid >> 4;
    const int nt   = bid & 15;       // 16 tiles of 128

    const __half* hb = g_h + (size_t)(e * TPE) * HID;
    const float* w2b = w2 + (size_t)e * HID * DIM + nt * 128;

    const int wm = wid >> 2, wn = wid & 3;
    const int mbase = wm * 64, nbase = wn * 32;
    const int blk = lane >> 3, r = lane & 7;

    const int am = tid >> 3, aq = tid & 7;     // A rows am + j*64
    const int nb = tid & 127, kg = tid >> 7;   // B: n row, k-octs kg, kg+4

    auto cpA = [&](int s) {
        const uint32_t buf = sbase + (uint32_t)(s & 3) * ABUF_SZ;
        const int k0 = s * 64;
        #pragma unroll
        for (int j = 0; j < 4; j++) {
            int m = am + j * 64;
            cp16(buf + SWZ(m * 128 + aq * 16), hb + (size_t)m * HID + k0 + aq * 8);
        }
    };
    float vB[2][8];
    auto ldgB = [&](int s) {
        #pragma unroll
        for (int j = 0; j < 2; j++) {
            const int k0 = s * 64 + (kg + j * 4) * 8;
            #pragma unroll
            for (int t = 0; t < 8; t++)
                vB[j][t] = w2b[(size_t)(k0 + t) * DIM + nb];
        }
    };
    auto stsB = [&](int s) {
        char* buf = smem + BOFF + (size_t)(s & 3) * BSTG;
        #pragma unroll
        for (int j = 0; j < 2; j++) {
            uint4 t = { pkh2(vB[j][0], vB[j][1]), pkh2(vB[j][2], vB[j][3]),
                        pkh2(vB[j][4], vB[j][5]), pkh2(vB[j][6], vB[j][7]) };
            *(uint4*)(buf + nb * 144 + (kg + j * 4) * 16) = t;
        }
    };

    float acc[4][4][4];
    #pragma unroll
    for (int i = 0; i < 4; i++)
        #pragma unroll
        for (int j = 0; j < 4; j++)
            #pragma unroll
            for (int k = 0; k < 4; k++) acc[i][j][k] = 0.f;

    // prologue
    ldgB(0); stsB(0);
    ldgB(1); stsB(1);
    ldgB(2);
    cpA(0); CP_COMMIT();
    cpA(1); CP_COMMIT();
    cpA(2); CP_COMMIT();

    const int q = lane >> 3, rr = lane & 7;
    const uint32_t brel = (uint32_t)(nbase + (q & 1) * 8 + rr) * 144 + (uint32_t)(q >> 1) * 16;

    const int NS = HID / 64;   // 16
    #pragma unroll 1
    for (int s = 0; s < NS; s++) {
        CP_WAIT2();
        __syncthreads();
        const uint32_t aA = sbase + (uint32_t)(s & 3) * ABUF_SZ;
        const uint32_t aB = sbase + BOFF + (uint32_t)(s & 3) * BSTG + brel;
        #pragma unroll
        for (int kk = 0; kk < 4; kk++) {
            uint32_t af[4][4];
            #pragma unroll
            for (int m2 = 0; m2 < 4; m2++)
                ldsm4(af[m2], aA + SWZ((mbase + m2 * 16 + (blk & 1) * 8 + r) * 128 + kk * 32 + (blk >> 1) * 16));
            uint32_t bf[2][4];
            ldsm4(bf[0], aB + kk * 32);           // n rows nbase..+15
            ldsm4(bf[1], aB + 2304 + kk * 32);    // n rows nbase+16..+31
            #pragma unroll
            for (int m2 = 0; m2 < 4; m2++)
                #pragma unroll
                for (int p = 0; p < 4; p++)
                    mma16(acc[m2][p], af[m2], bf[p >> 1][p & 1], bf[p >> 1][(p & 1) + 2]);
        }
        if (s + 2 < NS) stsB(s + 2);
        if (s + 3 < NS) { ldgB(s + 3); cpA(s + 3); }
        CP_COMMIT();
    }

    const int g = lane >> 2, t4 = lane & 3;
    float* ob = out + (size_t)(e * TPE) * DIM + nt * 128;
    #pragma unroll
    for (int m2 = 0; m2 < 4; m2++) {
        #pragma unroll
        for (int p = 0; p < 4; p++) {
            int row = mbase + m2 * 16 + g;
            int col = nbase + p * 8 + 2 * t4;
            float* r0 = ob + (size_t)row * DIM + col;
            float* r1p = r0 + 8 * DIM;
            *(float2*)r0 = make_float2(acc[m2][p][0], acc[m2][p][1]);
            *(float2*)r1p = make_float2(acc[m2][p][2], acc[m2][p][3]);
        }
    }
}

// ======================================================================
extern "C" void kernel_launch(void* const* d_in, const int* in_sizes, int n_in,
                              void* d_out, int out_size)
{
    (void)in_sizes; (void)n_in; (void)out_size;
    const float* x  = (const float*)d_in[0];
    const float* w1 = (const float*)d_in[1];
    const float* w2 = (const float*)d_in[2];
    const float* w3 = (const float*)d_in[3];
    float* out = (float*)d_out;

    static bool attr_set = false;
    if (!attr_set) {
        cudaFuncSetAttribute(moe_up_kernel,   cudaFuncAttributeMaxDynamicSharedMemorySize, SMEM_TOT);
        cudaFuncSetAttribute(moe_down_kernel, cudaFuncAttributeMaxDynamicSharedMemorySize, SMEM_TOT);
        attr_set = true;
    }

    preconv_kernel<<<2048, 256>>>(x);
    moe_up_kernel<<<NEXP * 16, 512, SMEM_TOT>>>(w1, w3);
    moe_down_kernel<<<NEXP * 16, 512, SMEM_TOT>>>(w2, out);
}